// round 2
// baseline (speedup 1.0000x reference)
#include <cuda_runtime.h>
#include <math.h>

#define Bv   2
#define Nv   4096
#define CIN  64
#define COUT 128
#define KNB  24
#define R2   0.0225f

// Output layout: pc (2*4096*6) | fout (2*128*4096) | pe (2*128*4096*24)
#define PC_ELEMS   (Bv*Nv*6)
#define FOUT_OFF   (PC_ELEMS)
#define FOUT_ELEMS (Bv*COUT*Nv)
#define PE_OFF     (FOUT_OFF + FOUT_ELEMS)

#define NSEG   (Bv*Nv)            // 8192 flat segments of 72 floats
#define DPLEN  (Bv*3*Nv*KNB)      // 589824

__device__ float g_f1[Bv*COUT*Nv];
__device__ float g_dp[DPLEN];
__device__ float g_ndp[DPLEN];
__device__ float g_nn[DPLEN];
__device__ int   g_idx[Bv*Nv*KNB];
__device__ int   g_jsel[NSEG*KNB];

// ---------------------------------------------------------------- pc copy
__global__ void k_copy(const float* __restrict__ pc, float* __restrict__ out) {
    int i = blockIdx.x * 256 + threadIdx.x;
    if (i < PC_ELEMS) out[i] = pc[i];
}

// ---------------------------------------------------------------- f1 = relu(bn(w1 @ f))
__global__ void k_f1(const float* __restrict__ f, const float* __restrict__ w1,
                     const float* __restrict__ g1, const float* __restrict__ b1) {
    int b = blockIdx.y;
    int col0 = blockIdx.x * 32;
    int t = threadIdx.x; // 128 threads = out channel
    __shared__ float fs[64][32];
    for (int e = t; e < 64 * 32; e += 128) {
        int row = e >> 5, col = e & 31;
        fs[row][col] = f[((size_t)b * CIN + row) * Nv + col0 + col];
    }
    __syncthreads();
    float acc[32];
#pragma unroll
    for (int i = 0; i < 32; i++) acc[i] = 0.f;
    const float* wr = w1 + t * CIN;
    for (int ci = 0; ci < CIN; ci++) {
        float wv = __ldg(wr + ci);
        const float4* r = (const float4*)&fs[ci][0];
#pragma unroll
        for (int q = 0; q < 8; q++) {
            float4 v = r[q];
            acc[4*q+0] = fmaf(wv, v.x, acc[4*q+0]);
            acc[4*q+1] = fmaf(wv, v.y, acc[4*q+1]);
            acc[4*q+2] = fmaf(wv, v.z, acc[4*q+2]);
            acc[4*q+3] = fmaf(wv, v.w, acc[4*q+3]);
        }
    }
    float inv = rsqrtf(1.0f + 1e-5f);
    float s = g1[t] * inv, bb = b1[t];
    float* o = g_f1 + ((size_t)b * COUT + t) * Nv + col0;
#pragma unroll
    for (int i = 0; i < 32; i++) o[i] = fmaxf(fmaf(acc[i], s, bb), 0.f);
}

// ---------------------------------------------------------------- ball query 1 (first K indices within radius)
// Chunked support staging: 2 x 2048 points (24KB) + per-warp hit buffers.
// Total static smem ~27.6KB, below the 48KB default limit.
__global__ void k_ballq(const float* __restrict__ pc) {
    __shared__ float sx[2048], sy[2048], sz[2048];
    __shared__ int   widx[8][KNB];
    __shared__ float sdp[8][3][KNB];
    int b = blockIdx.y;
    int t = threadIdx.x; // 256
    int w = t >> 5, lane = t & 31;
    int n = blockIdx.x * 8 + w;
    const float* qp = pc + ((size_t)b * Nv + n) * 6;
    float qx = qp[0], qy = qp[1], qz = qp[2];
    float qq = qx*qx + qy*qy + qz*qz;
    int count = 0;
    for (int c = 0; c < 2; c++) {
        __syncthreads();
        for (int i = t; i < 2048; i += 256) {
            const float* pp = pc + ((size_t)b * Nv + c * 2048 + i) * 6;
            sx[i] = pp[0]; sy[i] = pp[1]; sz[i] = pp[2];
        }
        __syncthreads();
        if (count >= KNB) continue;
        for (int base = 0; base < 2048; base += 32) {
            int s = base + lane;
            float x = sx[s], y = sy[s], z = sz[s];
            float ss = x*x + y*y + z*z;
            float d2 = qq + ss - 2.f * (qx*x + qy*y + qz*z);
            bool hit = d2 < R2;
            unsigned m = __ballot_sync(0xffffffffu, hit);
            if (hit) {
                int r = count + __popc(m & ((1u << lane) - 1u));
                if (r < KNB) {
                    widx[w][r] = c * 2048 + s;
                    sdp[w][0][r] = x - qx;
                    sdp[w][1][r] = y - qy;
                    sdp[w][2][r] = z - qz;
                }
            }
            count += __popc(m);
            if (count >= KNB) break;
        }
    }
    __syncwarp();
    int cnt = count > KNB ? KNB : count;
    if (lane < KNB) {
        // cnt >= 1 always (query is its own neighbor, d2 ~ 0 < R2)
        int src = (lane < cnt) ? lane : 0;
        size_t gi = ((size_t)b * Nv + n) * KNB + lane;
        g_idx[gi] = widx[w][src];
        g_dp[(((size_t)b*3 + 0) * Nv + n) * KNB + lane] = sdp[w][0][src];
        g_dp[(((size_t)b*3 + 1) * Nv + n) * KNB + lane] = sdp[w][1][src];
        g_dp[(((size_t)b*3 + 2) * Nv + n) * KNB + lane] = sdp[w][2][src];
    }
}

// ---------------------------------------------------------------- FPS on flat 72-float segments
__global__ void k_fps() {
    int t = threadIdx.x, w = t >> 5, lane = t & 31;
    int g = blockIdx.x * 8 + w;
    __shared__ float sp[8][KNB][3];
    __shared__ int   sperm[8][KNB];
    const float* seg = g_dp + (size_t)g * 72;
    if (lane < KNB) {
        sp[w][lane][0] = seg[lane*3];
        sp[w][lane][1] = seg[lane*3+1];
        sp[w][lane][2] = seg[lane*3+2];
    }
    __syncwarp();
    float px = 0.f, py = 0.f, pz = 0.f, dist = 1e10f;
    if (lane < KNB) { px = sp[w][lane][0]; py = sp[w][lane][1]; pz = sp[w][lane][2]; }
    int last = 0;
    if (lane == 0) sperm[w][0] = 0;
    for (int i = 1; i < KNB; i++) {
        float lx = __shfl_sync(0xffffffffu, px, last);
        float ly = __shfl_sync(0xffffffffu, py, last);
        float lz = __shfl_sync(0xffffffffu, pz, last);
        float dx = px - lx, dy = py - ly, dz = pz - lz;
        float d = dx*dx + dy*dy + dz*dz;
        if (lane < KNB) dist = fminf(dist, d);
        float v = (lane < KNB) ? dist : -1.f;
        int bi = lane;
#pragma unroll
        for (int off = 16; off; off >>= 1) {
            float ov = __shfl_down_sync(0xffffffffu, v, off);
            int   oi = __shfl_down_sync(0xffffffffu, bi, off);
            if (ov > v || (ov == v && oi < bi)) { v = ov; bi = oi; }
        }
        last = __shfl_sync(0xffffffffu, bi, 0);
        if (lane == 0) sperm[w][i] = last;
    }
    __syncwarp();
    float* o = g_ndp + (size_t)g * 72;
    if (lane < KNB) {
        int s = sperm[w][lane];
        o[lane*3]   = sp[w][s][0];
        o[lane*3+1] = sp[w][s][1];
        o[lane*3+2] = sp[w][s][2];
    }
}

// ---------------------------------------------------------------- delta MLP (3->32->16->3), new_dp += delta
__global__ void k_mlp(const float* __restrict__ wd1, const float* __restrict__ gd1, const float* __restrict__ bd1,
                      const float* __restrict__ wd2, const float* __restrict__ gd2, const float* __restrict__ bd2,
                      const float* __restrict__ wd3, const float* __restrict__ gd3, const float* __restrict__ bd3) {
    __shared__ float s_wd1[96], s_a1[32], s_b1[32];
    __shared__ float s_wd2[512], s_a2[16], s_b2[16];
    __shared__ float s_wd3[48], s_a3[3], s_b3[3];
    int t = threadIdx.x; // 256
    float inv = rsqrtf(1.0f + 1e-5f);
    if (t < 96) s_wd1[t] = wd1[t];
    if (t < 32) { s_a1[t] = gd1[t] * inv; s_b1[t] = bd1[t]; }
    for (int i = t; i < 512; i += 256) s_wd2[i] = wd2[i];
    if (t < 16) { s_a2[t] = gd2[t] * inv; s_b2[t] = bd2[t]; }
    if (t >= 128 && t < 176) s_wd3[t-128] = wd3[t-128];
    if (t >= 176 && t < 179) { s_a3[t-176] = gd3[t-176] * inv; s_b3[t-176] = bd3[t-176]; }
    __syncthreads();
    int p = blockIdx.x * 256 + t;
    if (p >= Bv * Nv * KNB) return;
    int b = p / (Nv * KNB);
    int rem = p % (Nv * KNB);
    int n = rem / KNB, k = rem % KNB;
    size_t base = (((size_t)b * 3) * Nv + n) * KNB + k;
    const size_t CS = (size_t)Nv * KNB; // channel stride 98304
    float x0 = g_ndp[base], x1 = g_ndp[base + CS], x2 = g_ndp[base + 2*CS];
    float h1[32];
#pragma unroll
    for (int o = 0; o < 32; o++) {
        float a = s_wd1[o*3]*x0 + s_wd1[o*3+1]*x1 + s_wd1[o*3+2]*x2;
        h1[o] = fmaxf(fmaf(a, s_a1[o], s_b1[o]), 0.f);
    }
    float h2[16];
#pragma unroll
    for (int o = 0; o < 16; o++) {
        float a = 0.f;
#pragma unroll
        for (int ci = 0; ci < 32; ci++) a = fmaf(s_wd2[o*32+ci], h1[ci], a);
        h2[o] = fmaxf(fmaf(a, s_a2[o], s_b2[o]), 0.f);
    }
#pragma unroll
    for (int c = 0; c < 3; c++) {
        float a = 0.f;
#pragma unroll
        for (int ci = 0; ci < 16; ci++) a = fmaf(s_wd3[c*16+ci], h2[ci], a);
        float d = fmaf(a, s_a3[c], s_b3[c]);
        float xin = (c == 0) ? x0 : (c == 1) ? x1 : x2;
        g_ndp[base + (size_t)c * CS] = xin + d;
    }
}

// ---------------------------------------------------------------- NN query (k=1) on segments: q=new_dp, s=dp
__global__ void k_nnq() {
    int t = threadIdx.x, w = t >> 5, lane = t & 31;
    int g = blockIdx.x * 8 + w;
    __shared__ float sp[8][KNB][3];
    __shared__ float sss[8][KNB];
    const float* sseg = g_dp + (size_t)g * 72;
    if (lane < KNB) {
        float x = sseg[lane*3], y = sseg[lane*3+1], z = sseg[lane*3+2];
        sp[w][lane][0] = x; sp[w][lane][1] = y; sp[w][lane][2] = z;
        sss[w][lane] = x*x + y*y + z*z;
    }
    __syncwarp();
    if (lane < KNB) {
        const float* qseg = g_ndp + (size_t)g * 72;
        float qx = qseg[lane*3], qy = qseg[lane*3+1], qz = qseg[lane*3+2];
        float qq = qx*qx + qy*qy + qz*qz;
        int found = -1;
        for (int jj = 0; jj < KNB; jj++) {
            float d2 = qq + sss[w][jj] - 2.f * (qx*sp[w][jj][0] + qy*sp[w][jj][1] + qz*sp[w][jj][2]);
            if (d2 < R2) { found = jj; break; }
        }
        int j = found < 0 ? 0 : found;
        g_jsel[g * KNB + lane] = j;
        float* o = g_nn + (size_t)g * 72;
        o[0*KNB + lane] = sp[w][j][0] - qx;
        o[1*KNB + lane] = sp[w][j][1] - qy;
        o[2*KNB + lane] = sp[w][j][2] - qz;
    }
}

// ---------------------------------------------------------------- fused final: fj2 gather, ww GEMM, softmax, pe, fout
__global__ __launch_bounds__(128) void k_final(
    const float* __restrict__ ww, const float* __restrict__ gw, const float* __restrict__ bw,
    const float* __restrict__ wc2, const float* __restrict__ gc2, const float* __restrict__ bc2,
    float* __restrict__ out) {
    int n = blockIdx.x, b = blockIdx.y;
    int t = threadIdx.x; // 128 = output channel
    __shared__ float fj2s[COUT][KNB];     // 12288 B
    __shared__ float wws[COUT][33];       // padded, conflict-free
    __shared__ float sdp2[3][KNB];
    __shared__ int   sidxn[KNB];

    if (t < KNB) sidxn[t] = g_idx[((size_t)b * Nv + n) * KNB + t];
    if (t >= 32 && t < 32 + 72) {
        int e = t - 32;
        sdp2[e / KNB][e % KNB] = g_nn[(((size_t)b*3 + e / KNB) * Nv + n) * KNB + (e % KNB)];
    }
    __syncthreads();
    {
        const float* f1row = g_f1 + ((size_t)b * COUT + t) * Nv;
        int grow = ((b * COUT + t) * 32 + (n >> 7)) * KNB;
#pragma unroll
        for (int k = 0; k < KNB; k++)
            fj2s[t][k] = f1row[sidxn[g_jsel[grow + k]]];
    }
    float acc[KNB];
#pragma unroll
    for (int k = 0; k < KNB; k++) acc[k] = 0.f;

    for (int tile = 0; tile < 4; tile++) {
        __syncthreads();
        const float* wsrc = ww + t * COUT + tile * 32;
#pragma unroll
        for (int q = 0; q < 8; q++) {
            float4 v = ((const float4*)wsrc)[q];
            wws[t][4*q+0] = v.x; wws[t][4*q+1] = v.y;
            wws[t][4*q+2] = v.z; wws[t][4*q+3] = v.w;
        }
        __syncthreads();
#pragma unroll
        for (int ci = 0; ci < 32; ci++) {
            float wv = wws[t][ci];
            const float4* r = (const float4*)&fj2s[tile*32 + ci][0];
#pragma unroll
            for (int q = 0; q < 6; q++) {
                float4 v = r[q];
                acc[4*q+0] = fmaf(wv, v.x, acc[4*q+0]);
                acc[4*q+1] = fmaf(wv, v.y, acc[4*q+1]);
                acc[4*q+2] = fmaf(wv, v.z, acc[4*q+2]);
                acc[4*q+3] = fmaf(wv, v.w, acc[4*q+3]);
            }
        }
    }
    float inv = rsqrtf(1.0f + 1e-5f);
    float sw = gw[t] * inv, bwv = bw[t];
    float mx = -3.402823e38f;
#pragma unroll
    for (int k = 0; k < KNB; k++) {
        acc[k] = fmaf(acc[k], sw, bwv);
        mx = fmaxf(mx, acc[k]);
    }
    float sum = 0.f;
#pragma unroll
    for (int k = 0; k < KNB; k++) { float e = expf(acc[k] - mx); acc[k] = e; sum += e; }
    float rs = 1.f / sum;
    float w0 = wc2[t*3], w1v = wc2[t*3+1], w2v = wc2[t*3+2];
    float sc = gc2[t] * inv, bc = bc2[t];
    float pe[KNB];
    float fo = -3.402823e38f;
#pragma unroll
    for (int k = 0; k < KNB; k++) {
        float v = w0 * sdp2[0][k] + w1v * sdp2[1][k] + w2v * sdp2[2][k];
        v = fmaxf(fmaf(v, sc, bc), 0.f);
        pe[k] = v;
        fo = fmaxf(fo, (v + fj2s[t][k]) * (acc[k] * rs));
    }
    float* po = out + PE_OFF + (((size_t)b * COUT + t) * Nv + n) * KNB;
#pragma unroll
    for (int q = 0; q < 6; q++) {
        float4 v = make_float4(pe[4*q], pe[4*q+1], pe[4*q+2], pe[4*q+3]);
        ((float4*)po)[q] = v;
    }
    out[FOUT_OFF + ((size_t)b * COUT + t) * Nv + n] = fo;
}

// ----------------------------------------------------------------
extern "C" void kernel_launch(void* const* d_in, const int* in_sizes, int n_in,
                              void* d_out, int out_size) {
    const float* pc  = (const float*)d_in[0];
    const float* f   = (const float*)d_in[1];
    const float* w1  = (const float*)d_in[3];
    const float* g1  = (const float*)d_in[4];
    const float* b1  = (const float*)d_in[5];
    const float* wd1 = (const float*)d_in[6];
    const float* gd1 = (const float*)d_in[7];
    const float* bd1 = (const float*)d_in[8];
    const float* wd2 = (const float*)d_in[9];
    const float* gd2 = (const float*)d_in[10];
    const float* bd2 = (const float*)d_in[11];
    const float* wd3 = (const float*)d_in[12];
    const float* gd3 = (const float*)d_in[13];
    const float* bd3 = (const float*)d_in[14];
    const float* ww  = (const float*)d_in[15];
    const float* gw  = (const float*)d_in[16];
    const float* bw  = (const float*)d_in[17];
    const float* wc2 = (const float*)d_in[18];
    const float* gc2 = (const float*)d_in[19];
    const float* bc2 = (const float*)d_in[20];
    float* out = (float*)d_out;

    k_copy<<<(PC_ELEMS + 255) / 256, 256>>>(pc, out);
    k_f1<<<dim3(Nv / 32, Bv), 128>>>(f, w1, g1, b1);
    k_ballq<<<dim3(Nv / 8, Bv), 256>>>(pc);
    k_fps<<<NSEG / 8, 256>>>();
    k_mlp<<<(Bv * Nv * KNB) / 256, 256>>>(wd1, gd1, bd1, wd2, gd2, bd2, wd3, gd3, bd3);
    k_nnq<<<NSEG / 8, 256>>>();
    k_final<<<dim3(Nv, Bv), 128>>>(ww, gw, bw, wc2, gc2, bc2, out);
}

// round 4
// speedup vs baseline: 1.6122x; 1.6122x over previous
#include <cuda_runtime.h>
#include <math.h>

#define Bv   2
#define Nv   4096
#define CIN  64
#define COUT 128
#define KNB  24
#define R2   0.0225f

// Output layout: pc (2*4096*6) | fout (2*128*4096) | pe (2*128*4096*24)
#define PC_ELEMS   (Bv*Nv*6)
#define FOUT_OFF   (PC_ELEMS)
#define FOUT_ELEMS (Bv*COUT*Nv)
#define PE_OFF     (FOUT_OFF + FOUT_ELEMS)

#define NSEG   (Bv*Nv)            // 8192 flat segments of 72 floats
#define DPLEN  (Bv*3*Nv*KNB)      // 589824

__device__ float g_f1t[Bv*Nv*COUT];   // transposed  [b][n][c]
__device__ float g_dp[DPLEN];
__device__ float g_ndp[DPLEN];
__device__ float g_nn[DPLEN];
__device__ int   g_idx[Bv*Nv*KNB];
__device__ int   g_jsel[NSEG*KNB];

// ---------------------------------------------------------------- pc copy
__global__ void k_copy(const float* __restrict__ pc, float* __restrict__ out) {
    int i = blockIdx.x * 256 + threadIdx.x;
    if (i < PC_ELEMS) out[i] = pc[i];
}

// ---------------------------------------------------------------- f1 = relu(bn(w1 @ f)); store transposed [b][n][c]
__global__ void k_f1(const float* __restrict__ f, const float* __restrict__ w1,
                     const float* __restrict__ g1, const float* __restrict__ b1) {
    int b = blockIdx.y;
    int col0 = blockIdx.x * 32;
    int t = threadIdx.x; // 128 threads = out channel
    __shared__ float fs[64][32];
    for (int e = t; e < 64 * 32; e += 128) {
        int row = e >> 5, col = e & 31;
        fs[row][col] = f[((size_t)b * CIN + row) * Nv + col0 + col];
    }
    __syncthreads();
    float acc[32];
#pragma unroll
    for (int i = 0; i < 32; i++) acc[i] = 0.f;
    const float* wr = w1 + t * CIN;
    for (int ci = 0; ci < CIN; ci++) {
        float wv = __ldg(wr + ci);
        const float4* r = (const float4*)&fs[ci][0];
#pragma unroll
        for (int q = 0; q < 8; q++) {
            float4 v = r[q];
            acc[4*q+0] = fmaf(wv, v.x, acc[4*q+0]);
            acc[4*q+1] = fmaf(wv, v.y, acc[4*q+1]);
            acc[4*q+2] = fmaf(wv, v.z, acc[4*q+2]);
            acc[4*q+3] = fmaf(wv, v.w, acc[4*q+3]);
        }
    }
    float inv = rsqrtf(1.0f + 1e-5f);
    float s = g1[t] * inv, bb = b1[t];
    float* ot = g_f1t + ((size_t)b * Nv + col0) * COUT + t;
#pragma unroll
    for (int i = 0; i < 32; i++)
        ot[(size_t)i * COUT] = fmaxf(fmaf(acc[i], s, bb), 0.f);
}

// ---------------------------------------------------------------- ball query 1 (first K indices within radius)
__global__ void k_ballq(const float* __restrict__ pc) {
    __shared__ float sx[2048], sy[2048], sz[2048];
    __shared__ int   widx[8][KNB];
    __shared__ float sdp[8][3][KNB];
    int b = blockIdx.y;
    int t = threadIdx.x; // 256
    int w = t >> 5, lane = t & 31;
    int n = blockIdx.x * 8 + w;
    const float* qp = pc + ((size_t)b * Nv + n) * 6;
    float qx = qp[0], qy = qp[1], qz = qp[2];
    float qq = qx*qx + qy*qy + qz*qz;
    int count = 0;
    for (int c = 0; c < 2; c++) {
        __syncthreads();
        for (int i = t; i < 2048; i += 256) {
            const float* pp = pc + ((size_t)b * Nv + c * 2048 + i) * 6;
            sx[i] = pp[0]; sy[i] = pp[1]; sz[i] = pp[2];
        }
        __syncthreads();
        if (count >= KNB) continue;
        for (int base = 0; base < 2048; base += 32) {
            int s = base + lane;
            float x = sx[s], y = sy[s], z = sz[s];
            float ss = x*x + y*y + z*z;
            float d2 = qq + ss - 2.f * (qx*x + qy*y + qz*z);
            bool hit = d2 < R2;
            unsigned m = __ballot_sync(0xffffffffu, hit);
            if (hit) {
                int r = count + __popc(m & ((1u << lane) - 1u));
                if (r < KNB) {
                    widx[w][r] = c * 2048 + s;
                    sdp[w][0][r] = x - qx;
                    sdp[w][1][r] = y - qy;
                    sdp[w][2][r] = z - qz;
                }
            }
            count += __popc(m);
            if (count >= KNB) break;
        }
    }
    __syncwarp();
    int cnt = count > KNB ? KNB : count;
    if (lane < KNB) {
        int src = (lane < cnt) ? lane : 0;
        size_t gi = ((size_t)b * Nv + n) * KNB + lane;
        g_idx[gi] = widx[w][src];
        g_dp[(((size_t)b*3 + 0) * Nv + n) * KNB + lane] = sdp[w][0][src];
        g_dp[(((size_t)b*3 + 1) * Nv + n) * KNB + lane] = sdp[w][1][src];
        g_dp[(((size_t)b*3 + 2) * Nv + n) * KNB + lane] = sdp[w][2][src];
    }
}

// ---------------------------------------------------------------- FPS on flat 72-float segments
__global__ void k_fps() {
    int t = threadIdx.x, w = t >> 5, lane = t & 31;
    int g = blockIdx.x * 8 + w;
    __shared__ float sp[8][KNB][3];
    __shared__ int   sperm[8][KNB];
    const float* seg = g_dp + (size_t)g * 72;
    if (lane < KNB) {
        sp[w][lane][0] = seg[lane*3];
        sp[w][lane][1] = seg[lane*3+1];
        sp[w][lane][2] = seg[lane*3+2];
    }
    __syncwarp();
    float px = 0.f, py = 0.f, pz = 0.f, dist = 1e10f;
    if (lane < KNB) { px = sp[w][lane][0]; py = sp[w][lane][1]; pz = sp[w][lane][2]; }
    int last = 0;
    if (lane == 0) sperm[w][0] = 0;
    for (int i = 1; i < KNB; i++) {
        float lx = __shfl_sync(0xffffffffu, px, last);
        float ly = __shfl_sync(0xffffffffu, py, last);
        float lz = __shfl_sync(0xffffffffu, pz, last);
        float dx = px - lx, dy = py - ly, dz = pz - lz;
        float d = dx*dx + dy*dy + dz*dz;
        if (lane < KNB) dist = fminf(dist, d);
        float v = (lane < KNB) ? dist : -1.f;
        int bi = lane;
#pragma unroll
        for (int off = 16; off; off >>= 1) {
            float ov = __shfl_down_sync(0xffffffffu, v, off);
            int   oi = __shfl_down_sync(0xffffffffu, bi, off);
            if (ov > v || (ov == v && oi < bi)) { v = ov; bi = oi; }
        }
        last = __shfl_sync(0xffffffffu, bi, 0);
        if (lane == 0) sperm[w][i] = last;
    }
    __syncwarp();
    float* o = g_ndp + (size_t)g * 72;
    if (lane < KNB) {
        int s = sperm[w][lane];
        o[lane*3]   = sp[w][s][0];
        o[lane*3+1] = sp[w][s][1];
        o[lane*3+2] = sp[w][s][2];
    }
}

// ---------------------------------------------------------------- delta MLP (3->32->16->3), new_dp += delta
__global__ void k_mlp(const float* __restrict__ wd1, const float* __restrict__ gd1, const float* __restrict__ bd1,
                      const float* __restrict__ wd2, const float* __restrict__ gd2, const float* __restrict__ bd2,
                      const float* __restrict__ wd3, const float* __restrict__ gd3, const float* __restrict__ bd3) {
    __shared__ float s_wd1[96], s_a1[32], s_b1[32];
    __shared__ float s_wd2[512], s_a2[16], s_b2[16];
    __shared__ float s_wd3[48], s_a3[3], s_b3[3];
    int t = threadIdx.x; // 256
    float inv = rsqrtf(1.0f + 1e-5f);
    if (t < 96) s_wd1[t] = wd1[t];
    if (t < 32) { s_a1[t] = gd1[t] * inv; s_b1[t] = bd1[t]; }
    for (int i = t; i < 512; i += 256) s_wd2[i] = wd2[i];
    if (t < 16) { s_a2[t] = gd2[t] * inv; s_b2[t] = bd2[t]; }
    if (t >= 128 && t < 176) s_wd3[t-128] = wd3[t-128];
    if (t >= 176 && t < 179) { s_a3[t-176] = gd3[t-176] * inv; s_b3[t-176] = bd3[t-176]; }
    __syncthreads();
    int p = blockIdx.x * 256 + t;
    if (p >= Bv * Nv * KNB) return;
    int b = p / (Nv * KNB);
    int rem = p % (Nv * KNB);
    int n = rem / KNB, k = rem % KNB;
    size_t base = (((size_t)b * 3) * Nv + n) * KNB + k;
    const size_t CS = (size_t)Nv * KNB;
    float x0 = g_ndp[base], x1 = g_ndp[base + CS], x2 = g_ndp[base + 2*CS];
    float h1[32];
#pragma unroll
    for (int o = 0; o < 32; o++) {
        float a = s_wd1[o*3]*x0 + s_wd1[o*3+1]*x1 + s_wd1[o*3+2]*x2;
        h1[o] = fmaxf(fmaf(a, s_a1[o], s_b1[o]), 0.f);
    }
    float h2[16];
#pragma unroll
    for (int o = 0; o < 16; o++) {
        float a = 0.f;
#pragma unroll
        for (int ci = 0; ci < 32; ci++) a = fmaf(s_wd2[o*32+ci], h1[ci], a);
        h2[o] = fmaxf(fmaf(a, s_a2[o], s_b2[o]), 0.f);
    }
#pragma unroll
    for (int c = 0; c < 3; c++) {
        float a = 0.f;
#pragma unroll
        for (int ci = 0; ci < 16; ci++) a = fmaf(s_wd3[c*16+ci], h2[ci], a);
        float d = fmaf(a, s_a3[c], s_b3[c]);
        float xin = (c == 0) ? x0 : (c == 1) ? x1 : x2;
        g_ndp[base + (size_t)c * CS] = xin + d;
    }
}

// ---------------------------------------------------------------- NN query (k=1) on segments: q=new_dp, s=dp
__global__ void k_nnq() {
    int t = threadIdx.x, w = t >> 5, lane = t & 31;
    int g = blockIdx.x * 8 + w;
    __shared__ float sp[8][KNB][3];
    __shared__ float sss[8][KNB];
    const float* sseg = g_dp + (size_t)g * 72;
    if (lane < KNB) {
        float x = sseg[lane*3], y = sseg[lane*3+1], z = sseg[lane*3+2];
        sp[w][lane][0] = x; sp[w][lane][1] = y; sp[w][lane][2] = z;
        sss[w][lane] = x*x + y*y + z*z;
    }
    __syncwarp();
    if (lane < KNB) {
        const float* qseg = g_ndp + (size_t)g * 72;
        float qx = qseg[lane*3], qy = qseg[lane*3+1], qz = qseg[lane*3+2];
        float qq = qx*qx + qy*qy + qz*qz;
        int found = -1;
        for (int jj = 0; jj < KNB; jj++) {
            float d2 = qq + sss[w][jj] - 2.f * (qx*sp[w][jj][0] + qy*sp[w][jj][1] + qz*sp[w][jj][2]);
            if (d2 < R2) { found = jj; break; }
        }
        int j = found < 0 ? 0 : found;
        g_jsel[g * KNB + lane] = j;
        float* o = g_nn + (size_t)g * 72;
        o[0*KNB + lane] = sp[w][j][0] - qx;
        o[1*KNB + lane] = sp[w][j][1] - qy;
        o[2*KNB + lane] = sp[w][j][2] - qz;
    }
}

// ---------------------------------------------------------------- fused final: 2 points/block, exact per-c gather GEMM
// fj2[b,c,n,k] = f1[b,c, idx[b,n, jsel[b*4096 + c*32 + (n>>7), k]]]
__global__ __launch_bounds__(128) void k_final(
    const float* __restrict__ ww, const float* __restrict__ gw, const float* __restrict__ bw,
    const float* __restrict__ wc2, const float* __restrict__ gc2, const float* __restrict__ bc2,
    float* __restrict__ out) {
    int n0 = blockIdx.x * 2, b = blockIdx.y;
    int t = threadIdx.x; // 128 = channel (c for gather, o for GEMM output)
    __shared__ float cols[KNB][COUT];      // 12 KB (transient per point)
    __shared__ float fj2s[2][KNB][COUT];   // 24 KB: [point][k][c]
    __shared__ float sdp2[2][3][KNB];
    __shared__ int   sidxn[2][KNB];

    // neighbor remap for this thread's channel (shared by both points: same n>>7)
    int grow = ((b * COUT + t) * 32 + (n0 >> 7)) * KNB;
    int jidx[KNB];
    {
        const int4* jp = (const int4*)(g_jsel + grow);
#pragma unroll
        for (int q = 0; q < 6; q++) {
            int4 v = jp[q];
            jidx[4*q+0] = v.x; jidx[4*q+1] = v.y;
            jidx[4*q+2] = v.z; jidx[4*q+3] = v.w;
        }
    }
    if (t < 2 * KNB) sidxn[t / KNB][t % KNB] = g_idx[((size_t)b * Nv + n0 + t / KNB) * KNB + (t % KNB)];
    for (int e = t; e < 2 * 72; e += 128) {
        int i = e / 72, r = e % 72;
        sdp2[i][r / KNB][r % KNB] = g_nn[(((size_t)b*3 + r / KNB) * Nv + n0 + i) * KNB + (r % KNB)];
    }

#pragma unroll
    for (int i = 0; i < 2; i++) {
        __syncthreads();
        // coalesced load of the 24 needed f1 columns (float4 over c)
        {
            int c4 = t & 31, jb = t >> 5;
#pragma unroll
            for (int r = 0; r < 6; r++) {
                int j = r * 4 + jb;
                ((float4*)&cols[j][0])[c4] =
                    ((const float4*)(g_f1t + ((size_t)b * Nv + sidxn[i][j]) * COUT))[c4];
            }
        }
        __syncthreads();
        // conflict-free shuffle: fj2s[i][k][t] = cols[jidx[k]][t]
#pragma unroll
        for (int k = 0; k < KNB; k++)
            fj2s[i][k][t] = cols[jidx[k]][t];
    }
    __syncthreads();

    // GEMM: acc[i][k] = sum_c ww[t,c] * fj2s[i][k][c]
    float acc[2][KNB];
#pragma unroll
    for (int i = 0; i < 2; i++)
#pragma unroll
        for (int k = 0; k < KNB; k++) acc[i][k] = 0.f;

#pragma unroll
    for (int tile = 0; tile < 4; tile++) {
        float wreg[32];
        const float4* wp = (const float4*)(ww + (size_t)t * COUT + tile * 32);
#pragma unroll
        for (int q = 0; q < 8; q++) {
            float4 v = __ldg(wp + q);
            wreg[4*q+0] = v.x; wreg[4*q+1] = v.y;
            wreg[4*q+2] = v.z; wreg[4*q+3] = v.w;
        }
#pragma unroll
        for (int i = 0; i < 2; i++) {
#pragma unroll
            for (int k = 0; k < KNB; k++) {
                const float4* fr = (const float4*)&fj2s[i][k][tile * 32];
                float a = acc[i][k];
#pragma unroll
                for (int q = 0; q < 8; q++) {
                    float4 v = fr[q];
                    a = fmaf(wreg[4*q+0], v.x, a);
                    a = fmaf(wreg[4*q+1], v.y, a);
                    a = fmaf(wreg[4*q+2], v.z, a);
                    a = fmaf(wreg[4*q+3], v.w, a);
                }
                acc[i][k] = a;
            }
        }
    }

    float inv = rsqrtf(1.0f + 1e-5f);
    float sw = gw[t] * inv, bwv = bw[t];
    float w0 = wc2[t*3], w1v = wc2[t*3+1], w2v = wc2[t*3+2];
    float sc = gc2[t] * inv, bc = bc2[t];

#pragma unroll
    for (int i = 0; i < 2; i++) {
        float mx = -3.402823e38f;
#pragma unroll
        for (int k = 0; k < KNB; k++) {
            acc[i][k] = fmaf(acc[i][k], sw, bwv);
            mx = fmaxf(mx, acc[i][k]);
        }
        float sum = 0.f;
#pragma unroll
        for (int k = 0; k < KNB; k++) { float e = __expf(acc[i][k] - mx); acc[i][k] = e; sum += e; }
        float rs = 1.f / sum;
        float pe[KNB];
        float fo = -3.402823e38f;
#pragma unroll
        for (int k = 0; k < KNB; k++) {
            float v = w0 * sdp2[i][0][k] + w1v * sdp2[i][1][k] + w2v * sdp2[i][2][k];
            v = fmaxf(fmaf(v, sc, bc), 0.f);
            pe[k] = v;
            fo = fmaxf(fo, (v + fj2s[i][k][t]) * (acc[i][k] * rs));
        }
        float* po = out + PE_OFF + (((size_t)b * COUT + t) * Nv + n0 + i) * KNB;
#pragma unroll
        for (int q = 0; q < 6; q++)
            ((float4*)po)[q] = make_float4(pe[4*q], pe[4*q+1], pe[4*q+2], pe[4*q+3]);
        out[FOUT_OFF + ((size_t)b * COUT + t) * Nv + n0 + i] = fo;
    }
}

// ----------------------------------------------------------------
extern "C" void kernel_launch(void* const* d_in, const int* in_sizes, int n_in,
                              void* d_out, int out_size) {
    const float* pc  = (const float*)d_in[0];
    const float* f   = (const float*)d_in[1];
    const float* w1  = (const float*)d_in[3];
    const float* g1  = (const float*)d_in[4];
    const float* b1  = (const float*)d_in[5];
    const float* wd1 = (const float*)d_in[6];
    const float* gd1 = (const float*)d_in[7];
    const float* bd1 = (const float*)d_in[8];
    const float* wd2 = (const float*)d_in[9];
    const float* gd2 = (const float*)d_in[10];
    const float* bd2 = (const float*)d_in[11];
    const float* wd3 = (const float*)d_in[12];
    const float* gd3 = (const float*)d_in[13];
    const float* bd3 = (const float*)d_in[14];
    const float* ww  = (const float*)d_in[15];
    const float* gw  = (const float*)d_in[16];
    const float* bw  = (const float*)d_in[17];
    const float* wc2 = (const float*)d_in[18];
    const float* gc2 = (const float*)d_in[19];
    const float* bc2 = (const float*)d_in[20];
    float* out = (float*)d_out;

    k_copy<<<(PC_ELEMS + 255) / 256, 256>>>(pc, out);
    k_f1<<<dim3(Nv / 32, Bv), 128>>>(f, w1, g1, b1);
    k_ballq<<<dim3(Nv / 8, Bv), 256>>>(pc);
    k_fps<<<NSEG / 8, 256>>>();
    k_mlp<<<(Bv * Nv * KNB) / 256, 256>>>(wd1, gd1, bd1, wd2, gd2, bd2, wd3, gd3, bd3);
    k_nnq<<<NSEG / 8, 256>>>();
    k_final<<<dim3(Nv / 2, Bv), 128>>>(ww, gw, bw, wc2, gc2, bc2, out);
}